// round 15
// baseline (speedup 1.0000x reference)
#include <cuda_runtime.h>
#include <cuda_fp16.h>

#define S 4096
#define D 1024
#define H 16

// ---------------------------------------------------------------------------
// Device-global scratch: pure fp16 (norm-averaged rel_err ~6e-4 < 1e-3).
// All MMAs fp16-in / fp32-accumulate.
// ---------------------------------------------------------------------------
__device__ __half g_x[S * D];
__device__ __half g_w[4][D * D];          // WQ, WK, WV, WO
__device__ __half g_q[S * D], g_k[S * D], g_v[S * D], g_a[S * D];

// ---------------------------------------------------------------------------
// Helpers
// ---------------------------------------------------------------------------
__device__ __forceinline__ unsigned smem_u32(const void* p) {
    return (unsigned)__cvta_generic_to_shared(p);
}

__device__ __forceinline__ unsigned pack_h2(float f0, float f1) {
    __half2 h = __floats2half2_rn(f0, f1);
    return *reinterpret_cast<unsigned*>(&h);
}

// single-instruction MUFU.EX2 (no libm wrapper)
__device__ __forceinline__ float ex2(float x) {
    float y;
    asm volatile("ex2.approx.ftz.f32 %0, %1;" : "=f"(y) : "f"(x));
    return y;
}

__device__ __forceinline__ void ldm_x4(unsigned addr, unsigned& r0, unsigned& r1,
                                       unsigned& r2, unsigned& r3) {
    asm volatile("ldmatrix.sync.aligned.m8n8.x4.shared.b16 {%0,%1,%2,%3},[%4];\n"
                 : "=r"(r0), "=r"(r1), "=r"(r2), "=r"(r3) : "r"(addr));
}

__device__ __forceinline__ void ldm_x4_t(unsigned addr, unsigned& r0, unsigned& r1,
                                         unsigned& r2, unsigned& r3) {
    asm volatile("ldmatrix.sync.aligned.m8n8.x4.trans.shared.b16 {%0,%1,%2,%3},[%4];\n"
                 : "=r"(r0), "=r"(r1), "=r"(r2), "=r"(r3) : "r"(addr));
}

__device__ __forceinline__ void mma_f16(float c[4], const unsigned a[4],
                                        const unsigned b[2]) {
    asm volatile(
        "mma.sync.aligned.m16n8k16.row.col.f32.f16.f16.f32 "
        "{%0,%1,%2,%3},{%4,%5,%6,%7},{%8,%9},{%0,%1,%2,%3};\n"
        : "+f"(c[0]), "+f"(c[1]), "+f"(c[2]), "+f"(c[3])
        : "r"(a[0]), "r"(a[1]), "r"(a[2]), "r"(a[3]), "r"(b[0]), "r"(b[1]));
}

__device__ __forceinline__ void cp16(uint4* dst_smem, const void* src) {
    unsigned d = smem_u32(dst_smem);
    asm volatile("cp.async.cg.shared.global [%0],[%1],16;\n" :: "r"(d), "l"(src));
}
#define CP_COMMIT() asm volatile("cp.async.commit_group;\n" ::: "memory")
#define CP_WAIT1()  asm volatile("cp.async.wait_group 1;\n" ::: "memory")

// ---------------------------------------------------------------------------
// Conversion kernels: fp32 -> fp16
// ---------------------------------------------------------------------------
__global__ __launch_bounds__(256) void conv_x_kernel(const float* __restrict__ x) {
    int i = (blockIdx.x * 256 + threadIdx.x) * 4;
    float4 v = *(const float4*)(x + i);
    ((unsigned*)g_x)[(i >> 1) + 0] = pack_h2(v.x, v.y);
    ((unsigned*)g_x)[(i >> 1) + 1] = pack_h2(v.z, v.w);
}

__global__ __launch_bounds__(256) void conv_w_kernel(const float* __restrict__ WQ,
                                                     const float* __restrict__ WK,
                                                     const float* __restrict__ WV,
                                                     const float* __restrict__ WO) {
    int i = (blockIdx.x * 256 + threadIdx.x) * 4;
    int m = i >> 20;
    int off = i & ((D * D) - 1);
    const float* W = (m == 0) ? WQ : (m == 1) ? WK : (m == 2) ? WV : WO;
    float4 v = *(const float4*)(W + off);
    ((unsigned*)g_w[m])[(off >> 1) + 0] = pack_h2(v.x, v.y);
    ((unsigned*)g_w[m])[(off >> 1) + 1] = pack_h2(v.z, v.w);
}

// ---------------------------------------------------------------------------
// GEMM core: C[128x64] = A[128xK] * B[64xK]^T, pure fp16, fp32 accum.
// 256 threads = 8 warps as 4(m) x 2(n); warp tile 32x32.
// K-step 64 (rows = 128B), cp.async double-buffered (2 x 24KB = 48KB).
// ---------------------------------------------------------------------------
__device__ __forceinline__ void gemm_core(const __half* __restrict__ A,
                                          const __half* __restrict__ B,
                                          int bm, int bn, float (&c)[2][4][4]) {
    __shared__ uint4 sm[3072];   // 48 KB
    const int tid = threadIdx.x;
    const int wid = tid >> 5, lane = tid & 31;
    const int wm = wid >> 1, wn = wid & 1;
    const int lr = (lane & 7) + ((lane >> 3) & 1) * 8;
    const int lc = lane >> 4;
    const unsigned sb = smem_u32(sm);

#pragma unroll
    for (int mt = 0; mt < 2; mt++)
#pragma unroll
        for (int nt = 0; nt < 4; nt++)
#pragma unroll
            for (int j = 0; j < 4; j++) c[mt][nt][j] = 0.0f;

    auto issue = [&](int ks, int s) {
        const int base = s * 1536;
#pragma unroll
        for (int t = 0; t < 4; t++) {           // A: 128 rows x 8 chunks
            int q = tid + t * 256;
            int r = q >> 3, cx = q & 7;
            int sw = r * 8 + (cx ^ (r & 7));
            cp16(&sm[base + sw], A + (size_t)(bm + r) * D + ks * 64 + cx * 8);
        }
#pragma unroll
        for (int t = 0; t < 2; t++) {           // B: 64 rows x 8 chunks
            int q = tid + t * 256;
            int r = q >> 3, cx = q & 7;
            int sw = r * 8 + (cx ^ (r & 7));
            cp16(&sm[base + 1024 + sw], B + (size_t)(bn + r) * D + ks * 64 + cx * 8);
        }
    };

    issue(0, 0); CP_COMMIT();
    issue(1, 1); CP_COMMIT();

    for (int i = 0; i < D / 64; i++) {
        CP_WAIT1();
        __syncthreads();
        const unsigned base = sb + (i & 1) * 24576;
#pragma unroll
        for (int kk = 0; kk < 4; kk++) {
            unsigned a[2][4], b[4][2];
#pragma unroll
            for (int mt = 0; mt < 2; mt++) {
                int row = wm * 32 + mt * 16 + lr;
                int off = (row * 8 + (((kk * 2) + lc) ^ (row & 7))) * 16;
                ldm_x4(base + off, a[mt][0], a[mt][1], a[mt][2], a[mt][3]);
            }
#pragma unroll
            for (int np = 0; np < 2; np++) {
                int rown = wn * 32 + np * 16 + lr;
                int off = (rown * 8 + (((kk * 2) + lc) ^ (rown & 7))) * 16;
                unsigned t0, t1, t2, t3;
                ldm_x4(base + 16384 + off, t0, t1, t2, t3);
                b[2 * np][0] = t0; b[2 * np][1] = t2;
                b[2 * np + 1][0] = t1; b[2 * np + 1][1] = t3;
            }
#pragma unroll
            for (int mt = 0; mt < 2; mt++)
#pragma unroll
                for (int nt = 0; nt < 4; nt++)
                    mma_f16(c[mt][nt], a[mt], b[nt]);
        }
        __syncthreads();
        if (i + 2 < D / 64) issue(i + 2, i & 1);
        CP_COMMIT();
    }
}

// Projections: Q/K/V = x @ W^T; Q scaled by (1/8)*log2(e) for base-2 softmax.
__global__ __launch_bounds__(256) void proj_gemm_kernel() {
    const int z = blockIdx.z;
    const int bm = blockIdx.y * 128, bn = blockIdx.x * 64;
    float c[2][4][4];
    gemm_core(g_x, g_w[z], bm, bn, c);

    __half* C = (z == 0) ? g_q : (z == 1) ? g_k : g_v;
    const float scale = (z == 0) ? 0.18033688f : 1.0f;   // 0.125 * log2(e)

    const int wid = threadIdx.x >> 5, lane = threadIdx.x & 31;
    const int wm = wid >> 1, wn = wid & 1;
#pragma unroll
    for (int mt = 0; mt < 2; mt++)
#pragma unroll
        for (int nt = 0; nt < 4; nt++) {
            int row = bm + wm * 32 + mt * 16 + (lane >> 2);
            int col = bn + wn * 32 + nt * 8 + (lane & 3) * 2;
            *(unsigned*)&C[(size_t)row * D + col] =
                pack_h2(c[mt][nt][0] * scale, c[mt][nt][1] * scale);
            *(unsigned*)&C[(size_t)(row + 8) * D + col] =
                pack_h2(c[mt][nt][2] * scale, c[mt][nt][3] * scale);
        }
}

// Output projection: out = A @ W_O^T (fp32)
__global__ __launch_bounds__(256) void out_gemm_kernel(float* __restrict__ out) {
    const int bm = blockIdx.y * 128, bn = blockIdx.x * 64;
    float c[2][4][4];
    gemm_core(g_a, g_w[3], bm, bn, c);

    const int wid = threadIdx.x >> 5, lane = threadIdx.x & 31;
    const int wm = wid >> 1, wn = wid & 1;
#pragma unroll
    for (int mt = 0; mt < 2; mt++)
#pragma unroll
        for (int nt = 0; nt < 4; nt++) {
            int row = bm + wm * 32 + mt * 16 + (lane >> 2);
            int col = bn + wn * 32 + nt * 8 + (lane & 3) * 2;
            float2 v0 = {c[mt][nt][0], c[mt][nt][1]};
            float2 v1 = {c[mt][nt][2], c[mt][nt][3]};
            *(float2*)&out[(size_t)row * D + col] = v0;
            *(float2*)&out[(size_t)(row + 8) * D + col] = v1;
        }
}

// ---------------------------------------------------------------------------
// Flash attention, pure fp16: 128-thread CTA = 4 warps; each warp owns
// 32 q rows (2 m16 tiles) -> K/V fragments loaded ONCE per warp feed BOTH
// q-tiles (1.7x less LDSM per unit work; L1 was the top pipe at 64.8%).
// 64-key KV tiles, cp.async double-buffered (2 x 16KB) + Q (16KB) = 48KB
// static smem. launch_bounds(128,2): 256-reg budget for the 128 fp32
// accumulators, no spills. Warp-vote rescale skip; base-2 softmax with raw
// ex2.approx.ftz.
// SMEM (uint4 idx): stage s at s*1024: K [0,512), V [512,1024); Q [2048,3072).
// ---------------------------------------------------------------------------
__global__ __launch_bounds__(128, 2) void attn_kernel() {
    __shared__ uint4 sm[3072];   // 48 KB

    const int tid = threadIdx.x, wid = tid >> 5, lane = tid & 31;
    const int h = blockIdx.y;
    const int qb = blockIdx.x * 128;       // 128 q rows per CTA
    const unsigned sb = smem_u32(sm);
    const int lr = (lane & 7) + ((lane >> 3) & 1) * 8;
    const int lc = lane >> 4;

    // ---- stage Q (128 rows x 128B = 16KB) ----
#pragma unroll
    for (int t = 0; t < 8; t++) {
        int idx = tid + t * 128;
        int row = idx >> 3, cx = idx & 7;
        int sw = row * 8 + (cx ^ (row & 7));
        cp16(&sm[2048 + sw], g_q + (size_t)(qb + row) * D + h * 64 + cx * 8);
    }
    CP_COMMIT();

    auto issue = [&](int kt, int s) {
        const int base = s * 1024;
#pragma unroll
        for (int t = 0; t < 4; t++) {
            int idx = tid + t * 128;
            int row = idx >> 3, cx = idx & 7;
            int sw = row * 8 + (cx ^ (row & 7));
            size_t g = (size_t)(kt * 64 + row) * D + h * 64 + cx * 8;
            cp16(&sm[base + sw], g_k + g);
            cp16(&sm[base + 512 + sw], g_v + g);
        }
    };

    issue(0, 0); CP_COMMIT();
    issue(1, 1); CP_COMMIT();

    float co[2][8][4];
#pragma unroll
    for (int qt = 0; qt < 2; qt++)
#pragma unroll
        for (int nt = 0; nt < 8; nt++)
#pragma unroll
            for (int j = 0; j < 4; j++) co[qt][nt][j] = 0.0f;
    float mx[2][2] = {{-1e30f, -1e30f}, {-1e30f, -1e30f}};
    float ll[2][2] = {{0.0f, 0.0f}, {0.0f, 0.0f}};

    for (int kt = 0; kt < S / 64; kt++) {
        CP_WAIT1();
        __syncthreads();
        const unsigned kbase = sb + (kt & 1) * 16384;
        const unsigned vbase = kbase + 8192;

        // ---- scores: 2 q-tiles x 64 keys per warp; K loaded once per kd ----
        float sc[2][8][4];
#pragma unroll
        for (int qt = 0; qt < 2; qt++)
#pragma unroll
            for (int nt = 0; nt < 8; nt++)
#pragma unroll
                for (int j = 0; j < 4; j++) sc[qt][nt][j] = 0.0f;

#pragma unroll
        for (int kd = 0; kd < 4; kd++) {
            unsigned q[2][4];
#pragma unroll
            for (int qt = 0; qt < 2; qt++) {
                int qrow = wid * 32 + qt * 16 + lr;
                int qoff = (qrow * 8 + (((kd * 2) + lc) ^ (qrow & 7))) * 16;
                ldm_x4(sb + 32768 + qoff, q[qt][0], q[qt][1], q[qt][2], q[qt][3]);
            }
#pragma unroll
            for (int np = 0; np < 4; np++) {
                int rown = np * 16 + lr;
                int off = (rown * 8 + (((kd * 2) + lc) ^ (rown & 7))) * 16;
                unsigned t0, t1, t2, t3;
                ldm_x4(kbase + off, t0, t1, t2, t3);
                unsigned b0[2] = {t0, t2}, b1[2] = {t1, t3};
                mma_f16(sc[0][2 * np], q[0], b0);
                mma_f16(sc[1][2 * np], q[1], b0);
                mma_f16(sc[0][2 * np + 1], q[0], b1);
                mma_f16(sc[1][2 * np + 1], q[1], b1);
            }
        }

        // ---- online softmax (base 2, raw MUFU.EX2), both q-tiles ----
        float tm[2][2] = {{-1e30f, -1e30f}, {-1e30f, -1e30f}};
#pragma unroll
        for (int qt = 0; qt < 2; qt++)
#pragma unroll
            for (int t = 0; t < 8; t++) {
                tm[qt][0] = fmaxf(tm[qt][0], fmaxf(sc[qt][t][0], sc[qt][t][1]));
                tm[qt][1] = fmaxf(tm[qt][1], fmaxf(sc[qt][t][2], sc[qt][t][3]));
            }
#pragma unroll
        for (int qt = 0; qt < 2; qt++)
#pragma unroll
            for (int j = 0; j < 2; j++) {
                tm[qt][j] = fmaxf(tm[qt][j], __shfl_xor_sync(0xffffffffu, tm[qt][j], 1));
                tm[qt][j] = fmaxf(tm[qt][j], __shfl_xor_sync(0xffffffffu, tm[qt][j], 2));
            }
        float mn[2][2];
        bool same = true;
#pragma unroll
        for (int qt = 0; qt < 2; qt++)
#pragma unroll
            for (int j = 0; j < 2; j++) {
                mn[qt][j] = fmaxf(mx[qt][j], tm[qt][j]);
                same = same && (mn[qt][j] == mx[qt][j]);
            }
        if (!__all_sync(0xffffffffu, same)) {
#pragma unroll
            for (int qt = 0; qt < 2; qt++) {
                float c0 = ex2(mx[qt][0] - mn[qt][0]);
                float c1 = ex2(mx[qt][1] - mn[qt][1]);
                mx[qt][0] = mn[qt][0]; mx[qt][1] = mn[qt][1];
                ll[qt][0] *= c0; ll[qt][1] *= c1;
#pragma unroll
                for (int nt = 0; nt < 8; nt++) {
                    co[qt][nt][0] *= c0; co[qt][nt][1] *= c0;
                    co[qt][nt][2] *= c1; co[qt][nt][3] *= c1;
                }
            }
        }
#pragma unroll
        for (int qt = 0; qt < 2; qt++) {
            float pa = 0.0f, pb = 0.0f, pc = 0.0f, pd = 0.0f;
#pragma unroll
            for (int t = 0; t < 8; t++) {
                sc[qt][t][0] = ex2(sc[qt][t][0] - mx[qt][0]); pa += sc[qt][t][0];
                sc[qt][t][1] = ex2(sc[qt][t][1] - mx[qt][0]); pb += sc[qt][t][1];
                sc[qt][t][2] = ex2(sc[qt][t][2] - mx[qt][1]); pc += sc[qt][t][2];
                sc[qt][t][3] = ex2(sc[qt][t][3] - mx[qt][1]); pd += sc[qt][t][3];
            }
            ll[qt][0] += pa + pb;
            ll[qt][1] += pc + pd;
        }

        // ---- O += P * V: V loaded once per u, feeds both q-tiles ----
#pragma unroll
        for (int u = 0; u < 4; u++) {
            unsigned pa[2][4];
#pragma unroll
            for (int qt = 0; qt < 2; qt++) {
                pa[qt][0] = pack_h2(sc[qt][2 * u][0], sc[qt][2 * u][1]);
                pa[qt][1] = pack_h2(sc[qt][2 * u][2], sc[qt][2 * u][3]);
                pa[qt][2] = pack_h2(sc[qt][2 * u + 1][0], sc[qt][2 * u + 1][1]);
                pa[qt][3] = pack_h2(sc[qt][2 * u + 1][2], sc[qt][2 * u + 1][3]);
            }
#pragma unroll
            for (int jp = 0; jp < 4; jp++) {
                int rowv = u * 16 + lr;
                int off = (rowv * 8 + (((jp * 2) + lc) ^ (rowv & 7))) * 16;
                unsigned t0, t1, t2, t3;
                ldm_x4_t(vbase + off, t0, t1, t2, t3);
                unsigned vA[2] = {t0, t1}, vB[2] = {t2, t3};
                mma_f16(co[0][2 * jp], pa[0], vA);
                mma_f16(co[1][2 * jp], pa[1], vA);
                mma_f16(co[0][2 * jp + 1], pa[0], vB);
                mma_f16(co[1][2 * jp + 1], pa[1], vB);
            }
        }
        __syncthreads();
        if (kt + 2 < S / 64) issue(kt + 2, kt & 1);
        CP_COMMIT();
    }

    // ---- finalize ----
#pragma unroll
    for (int qt = 0; qt < 2; qt++)
#pragma unroll
        for (int j = 0; j < 2; j++) {
            ll[qt][j] += __shfl_xor_sync(0xffffffffu, ll[qt][j], 1);
            ll[qt][j] += __shfl_xor_sync(0xffffffffu, ll[qt][j], 2);
        }

#pragma unroll
    for (int qt = 0; qt < 2; qt++) {
        float inv0 = 1.0f / ll[qt][0], inv1 = 1.0f / ll[qt][1];
        int row = qb + wid * 32 + qt * 16 + (lane >> 2);
#pragma unroll
        for (int nt = 0; nt < 8; nt++) {
            int col = h * 64 + nt * 8 + (lane & 3) * 2;
            *(unsigned*)&g_a[(size_t)row * D + col] =
                pack_h2(co[qt][nt][0] * inv0, co[qt][nt][1] * inv0);
            *(unsigned*)&g_a[(size_t)(row + 8) * D + col] =
                pack_h2(co[qt][nt][2] * inv1, co[qt][nt][3] * inv1);
        }
    }
}

// ---------------------------------------------------------------------------
// kernel_launch
// ---------------------------------------------------------------------------
extern "C" void kernel_launch(void* const* d_in, const int* in_sizes, int n_in,
                              void* d_out, int out_size) {
    const float* x  = (const float*)d_in[0];
    const float* WQ = (const float*)d_in[1];
    const float* WK = (const float*)d_in[2];
    const float* WV = (const float*)d_in[3];
    const float* WO = (const float*)d_in[4];
    float* out = (float*)d_out;

    conv_x_kernel<<<(S * D) / (256 * 4), 256>>>(x);
    conv_w_kernel<<<(4 * D * D) / (256 * 4), 256>>>(WQ, WK, WV, WO);

    dim3 gq(D / 64, S / 128, 3);
    proj_gemm_kernel<<<gq, 256>>>();

    dim3 ga(S / 128, H);
    attn_kernel<<<ga, 128>>>();

    dim3 go(D / 64, S / 128);
    out_gemm_kernel<<<go, 256>>>(out);
}